// round 1
// baseline (speedup 1.0000x reference)
#include <cuda_runtime.h>
#include <cstdint>

// Problem constants (fixed by the dataset)
#define NN   100000
#define EE   1600000
#define DINC 256
#define DHC  128

// ---------------- static device scratch (no allocations allowed) ----------------
__device__ int   d_deg[NN];
__device__ int   d_cursor[NN];
__device__ int   d_rowptr[NN + 1];
__device__ int   d_colidx[EE];
__device__ float d_dinv[NN];
__device__ float d_h  [(size_t)NN * DHC];  // GEMM output (dinv-scaled)
__device__ float d_h1 [(size_t)NN * DHC];  // layer-1 output (post agg+relu)
__device__ float d_z  [(size_t)NN * DHC];  // layer-2 output

// ---------------- degree count ----------------
__global__ void zero_deg_kernel(int n) {
    int i = blockIdx.x * blockDim.x + threadIdx.x;
    if (i < n) d_deg[i] = 0;
}

__global__ void count_deg_kernel(const int* __restrict__ dst, int e) {
    int i = blockIdx.x * blockDim.x + threadIdx.x;
    if (i < e) atomicAdd(&d_deg[dst[i]], 1);
}

__global__ void dinv_kernel(int n) {
    int i = blockIdx.x * blockDim.x + threadIdx.x;
    if (i < n) d_dinv[i] = rsqrtf((float)d_deg[i] + 1.0f);
}

// ---------------- single-block exclusive scan over degrees -> rowptr/cursor ----------------
__global__ void scan_kernel(int n) {
    __shared__ int wsum[32];
    __shared__ int s_carry;
    int t = threadIdx.x;
    if (t == 0) s_carry = 0;
    __syncthreads();
    int nChunks = (n + 1023) / 1024;
    for (int c = 0; c < nChunks; c++) {
        int i = c * 1024 + t;
        int v = (i < n) ? d_deg[i] : 0;
        int x = v;
        #pragma unroll
        for (int o = 1; o < 32; o <<= 1) {
            int y = __shfl_up_sync(0xffffffffu, x, o);
            if ((t & 31) >= o) x += y;
        }
        if ((t & 31) == 31) wsum[t >> 5] = x;
        __syncthreads();
        if (t < 32) {
            int s = wsum[t];
            #pragma unroll
            for (int o = 1; o < 32; o <<= 1) {
                int y = __shfl_up_sync(0xffffffffu, s, o);
                if (t >= o) s += y;
            }
            wsum[t] = s;   // inclusive scan of warp totals
        }
        __syncthreads();
        int warpOff = (t >= 32) ? wsum[(t >> 5) - 1] : 0;
        int incl = x + warpOff;
        int excl = incl - v + s_carry;
        if (i < n) { d_rowptr[i] = excl; d_cursor[i] = excl; }
        __syncthreads();                       // all reads of wsum / s_carry done
        if (t == 0) s_carry += wsum[31];       // chunk total
        __syncthreads();
    }
    if (t == 0) d_rowptr[n] = s_carry;
}

__global__ void fill_kernel(const int* __restrict__ src, const int* __restrict__ dst, int e) {
    int i = blockIdx.x * blockDim.x + threadIdx.x;
    if (i < e) {
        int pos = atomicAdd(&d_cursor[dst[i]], 1);
        d_colidx[pos] = src[i];
    }
}

// ---------------- fp32 GEMM: out[r][c] = dinv[r] * sum_k A[r][k] * W[k][c] ----------------
// BM=128 rows/block, BN=128 (full width), 256 threads, 8x8 per-thread tile,
// full W resident in shared, A staged in 16-deep k-chunks (transposed, padded).
template <int K>
__global__ void __launch_bounds__(256) gemm_scaled_kernel(
    const float* __restrict__ A, const float* __restrict__ W,
    float* __restrict__ out, int nrows)
{
    constexpr int BM = 128;
    constexpr int KC = 16;
    constexpr int SAP = 132;   // padded sA row stride (keeps 16B alignment: 132*4=528, 528%16==0)
    extern __shared__ float smem[];
    float* sW = smem;             // K*128
    float* sA = smem + K * 128;   // KC * SAP

    int tid = threadIdx.x;
    // stage full W into shared
    for (int i = tid * 4; i < K * 128; i += 256 * 4) {
        *(float4*)(sW + i) = *(const float4*)(W + i);
    }

    int blockRow = blockIdx.x * BM;
    int tx = tid & 15;    // col group: cols tx*8 .. tx*8+7
    int ty = tid >> 4;    // row group: rows ty*8 .. ty*8+7
    float acc[8][8];
    #pragma unroll
    for (int i = 0; i < 8; i++)
        #pragma unroll
        for (int j = 0; j < 8; j++) acc[i][j] = 0.0f;

    int lr = tid >> 2;          // 0..63
    int lk = (tid & 3) * 4;     // 0,4,8,12

    for (int k0 = 0; k0 < K; k0 += KC) {
        __syncthreads();   // protect sA reuse (also orders first-use of sW)
        #pragma unroll
        for (int rr = lr; rr < BM; rr += 64) {
            int grow = blockRow + rr;
            float4 v = make_float4(0.f, 0.f, 0.f, 0.f);
            if (grow < nrows) v = *(const float4*)(A + (size_t)grow * K + k0 + lk);
            sA[(lk + 0) * SAP + rr] = v.x;
            sA[(lk + 1) * SAP + rr] = v.y;
            sA[(lk + 2) * SAP + rr] = v.z;
            sA[(lk + 3) * SAP + rr] = v.w;
        }
        __syncthreads();

        #pragma unroll
        for (int k = 0; k < KC; k++) {
            const float* wr = sW + (k0 + k) * 128 + tx * 8;
            float4 w0 = *(const float4*)wr;
            float4 w1 = *(const float4*)(wr + 4);
            const float* ar = sA + k * SAP + ty * 8;
            float4 a0 = *(const float4*)ar;
            float4 a1 = *(const float4*)(ar + 4);
            float av[8] = {a0.x, a0.y, a0.z, a0.w, a1.x, a1.y, a1.z, a1.w};
            float wv[8] = {w0.x, w0.y, w0.z, w0.w, w1.x, w1.y, w1.z, w1.w};
            #pragma unroll
            for (int i = 0; i < 8; i++)
                #pragma unroll
                for (int j = 0; j < 8; j++)
                    acc[i][j] = fmaf(av[i], wv[j], acc[i][j]);
        }
    }

    #pragma unroll
    for (int i = 0; i < 8; i++) {
        int grow = blockRow + ty * 8 + i;
        if (grow < nrows) {
            float di = d_dinv[grow];
            float4 o0 = make_float4(acc[i][0] * di, acc[i][1] * di, acc[i][2] * di, acc[i][3] * di);
            float4 o1 = make_float4(acc[i][4] * di, acc[i][5] * di, acc[i][6] * di, acc[i][7] * di);
            float* op = out + (size_t)grow * 128 + tx * 8;
            *(float4*)op = o0;
            *(float4*)(op + 4) = o1;
        }
    }
}

// ---------------- aggregation: hout[i] = relu?( dinv[i]*(sum_{src} hin[src] + hin[i]) + b ) ----
// hin is already row-scaled by dinv (GEMM epilogue). One warp per node, float4 lanes.
__global__ void agg_kernel(const float* __restrict__ hin, float* __restrict__ hout,
                           const float* __restrict__ b, int n, int do_relu)
{
    int lane = threadIdx.x & 31;
    int node = blockIdx.x * (blockDim.x >> 5) + (threadIdx.x >> 5);
    if (node >= n) return;
    const float4* h4 = (const float4*)hin;
    float4 acc = h4[(size_t)node * 32 + lane];   // self term: hin[i] (= h[i]*dinv[i])
    int e   = d_rowptr[node];
    int end = d_rowptr[node + 1];
    for (; e + 3 < end; e += 4) {
        int s0 = d_colidx[e], s1 = d_colidx[e + 1], s2 = d_colidx[e + 2], s3 = d_colidx[e + 3];
        float4 v0 = h4[(size_t)s0 * 32 + lane];
        float4 v1 = h4[(size_t)s1 * 32 + lane];
        float4 v2 = h4[(size_t)s2 * 32 + lane];
        float4 v3 = h4[(size_t)s3 * 32 + lane];
        acc.x += v0.x + v1.x + v2.x + v3.x;
        acc.y += v0.y + v1.y + v2.y + v3.y;
        acc.z += v0.z + v1.z + v2.z + v3.z;
        acc.w += v0.w + v1.w + v2.w + v3.w;
    }
    for (; e < end; e++) {
        int s = d_colidx[e];
        float4 v = h4[(size_t)s * 32 + lane];
        acc.x += v.x; acc.y += v.y; acc.z += v.z; acc.w += v.w;
    }
    float di = d_dinv[node];
    float4 bb = ((const float4*)b)[lane];
    float4 r;
    r.x = fmaf(acc.x, di, bb.x);
    r.y = fmaf(acc.y, di, bb.y);
    r.z = fmaf(acc.z, di, bb.z);
    r.w = fmaf(acc.w, di, bb.w);
    if (do_relu) {
        r.x = fmaxf(r.x, 0.f); r.y = fmaxf(r.y, 0.f);
        r.z = fmaxf(r.z, 0.f); r.w = fmaxf(r.w, 0.f);
    }
    ((float4*)hout)[(size_t)node * 32 + lane] = r;
}

// ---------------- decode: out[e] = dot(z[a[e]], z[b[e]]) over 128 dims ----------------
__global__ void decode_kernel(const int* __restrict__ eli, float* __restrict__ out, int el)
{
    int gw = (blockIdx.x * blockDim.x + threadIdx.x) >> 5;
    int lane = threadIdx.x & 31;
    if (gw >= el) return;
    int a = eli[gw];
    int b = eli[el + gw];
    const float4* z4 = (const float4*)d_z;
    float4 va = z4[(size_t)a * 32 + lane];
    float4 vb = z4[(size_t)b * 32 + lane];
    float s = va.x * vb.x + va.y * vb.y + va.z * vb.z + va.w * vb.w;
    #pragma unroll
    for (int o = 16; o > 0; o >>= 1) s += __shfl_xor_sync(0xffffffffu, s, o);
    if (lane == 0) out[gw] = s;
}

// ---------------- launch ----------------
extern "C" void kernel_launch(void* const* d_in, const int* in_sizes, int n_in,
                              void* d_out, int out_size)
{
    const float* x   = (const float*)d_in[0];
    const int*   ei  = (const int*)d_in[1];   // [2, E]: src then dst
    const int*   eli = (const int*)d_in[2];   // [2, EL]
    const float* W1  = (const float*)d_in[3];
    const float* b1  = (const float*)d_in[4];
    const float* W2  = (const float*)d_in[5];
    const float* b2  = (const float*)d_in[6];
    float* out = (float*)d_out;

    int n  = in_sizes[0] / DINC;
    int e  = in_sizes[1] / 2;
    int el = in_sizes[2] / 2;

    const int* src = ei;
    const int* dst = ei + e;

    // opt-in to large dynamic shared (idempotent; not a stream op)
    static bool attr_set = false;
    if (!attr_set) {
        cudaFuncSetAttribute(gemm_scaled_kernel<DINC>,
                             cudaFuncAttributeMaxDynamicSharedMemorySize, 160 * 1024);
        cudaFuncSetAttribute(gemm_scaled_kernel<DHC>,
                             cudaFuncAttributeMaxDynamicSharedMemorySize, 96 * 1024);
        attr_set = true;
    }

    float* hbuf; cudaGetSymbolAddress((void**)&hbuf, d_h);
    float* h1;   cudaGetSymbolAddress((void**)&h1,   d_h1);
    float* z;    cudaGetSymbolAddress((void**)&z,    d_z);

    // 1) CSR build
    zero_deg_kernel<<<(n + 255) / 256, 256>>>(n);
    count_deg_kernel<<<(e + 255) / 256, 256>>>(dst, e);
    dinv_kernel<<<(n + 255) / 256, 256>>>(n);
    scan_kernel<<<1, 1024>>>(n);
    fill_kernel<<<(e + 255) / 256, 256>>>(src, dst, e);

    // 2) layer 1: h = (x@W1)*dinv ; h1 = relu(dinv*(gather-sum + self) + b1)
    {
        size_t smem = (size_t)(DINC * 128 + 16 * 132) * sizeof(float);
        gemm_scaled_kernel<DINC><<<(n + 127) / 128, 256, smem>>>(x, W1, hbuf, n);
        agg_kernel<<<(n + 7) / 8, 256>>>(hbuf, h1, b1, n, 1);
    }

    // 3) layer 2
    {
        size_t smem = (size_t)(DHC * 128 + 16 * 132) * sizeof(float);
        gemm_scaled_kernel<DHC><<<(n + 127) / 128, 256, smem>>>(h1, W2, hbuf, n);
        agg_kernel<<<(n + 7) / 8, 256>>>(hbuf, z, b2, n, 0);
    }

    // 4) decode
    decode_kernel<<<(el * 32 + 255) / 256, 256>>>(eli, out, el);
}

// round 2
// speedup vs baseline: 1.1196x; 1.1196x over previous
#include <cuda_runtime.h>
#include <cstdint>

// Problem constants (fixed by the dataset)
#define NN   100000
#define EE   1600000
#define DINC 256
#define DHC  128
#define NBLK ((NN + 1023) / 1024)   // 98 scan blocks

// ---------------- static device scratch (no allocations allowed) ----------------
__device__ int   d_deg[NN];
__device__ int   d_cursor[NN];
__device__ int   d_rowptr[NN + 1];
__device__ int   d_colidx[EE];
__device__ int   d_blocksum[NBLK];
__device__ int   d_blockoff[NBLK];
__device__ float d_dinv[NN];
__device__ float d_h  [(size_t)NN * DHC];  // GEMM output (dinv-scaled)
__device__ float d_h1 [(size_t)NN * DHC];  // layer-1 output (post agg+relu)
__device__ float d_z  [(size_t)NN * DHC];  // layer-2 output

// ---------------- degree count ----------------
__global__ void zero_deg_kernel(int n) {
    int i = blockIdx.x * blockDim.x + threadIdx.x;
    if (i < n) d_deg[i] = 0;
}

__global__ void count_deg_kernel(const int* __restrict__ dst, int e) {
    int i = blockIdx.x * blockDim.x + threadIdx.x;
    if (i < e) atomicAdd(&d_deg[dst[i]], 1);
}

__global__ void dinv_kernel(int n) {
    int i = blockIdx.x * blockDim.x + threadIdx.x;
    if (i < n) d_dinv[i] = rsqrtf((float)d_deg[i] + 1.0f);
}

// ---------------- hierarchical scan: pass 1 = per-block sum ----------------
__global__ void scan_reduce_kernel(int n) {
    __shared__ int wsum[32];
    int t = threadIdx.x;
    int i = blockIdx.x * 1024 + t;
    int v = (i < n) ? d_deg[i] : 0;
    #pragma unroll
    for (int o = 16; o > 0; o >>= 1) v += __shfl_xor_sync(0xffffffffu, v, o);
    if ((t & 31) == 0) wsum[t >> 5] = v;
    __syncthreads();
    if (t < 32) {
        int s = wsum[t];
        #pragma unroll
        for (int o = 16; o > 0; o >>= 1) s += __shfl_xor_sync(0xffffffffu, s, o);
        if (t == 0) d_blocksum[blockIdx.x] = s;
    }
}

// ---------------- pass 2: single-block exclusive scan of NBLK (<=1024) sums ----
__global__ void scan_spine_kernel(int nb, int n) {
    __shared__ int wsum[32];
    int t = threadIdx.x;
    int v = (t < nb) ? d_blocksum[t] : 0;
    int x = v;
    #pragma unroll
    for (int o = 1; o < 32; o <<= 1) {
        int y = __shfl_up_sync(0xffffffffu, x, o);
        if ((t & 31) >= o) x += y;
    }
    if ((t & 31) == 31) wsum[t >> 5] = x;
    __syncthreads();
    if (t < 32) {
        int s = wsum[t];
        #pragma unroll
        for (int o = 1; o < 32; o <<= 1) {
            int y = __shfl_up_sync(0xffffffffu, s, o);
            if (t >= o) s += y;
        }
        wsum[t] = s;  // inclusive scan of warp totals
    }
    __syncthreads();
    int warpOff = (t >= 32) ? wsum[(t >> 5) - 1] : 0;
    int excl = x + warpOff - v;
    if (t < nb) d_blockoff[t] = excl;
    if (t == 1023) d_rowptr[n] = x + warpOff;  // grand total
}

// ---------------- pass 3: per-block exclusive rescan + block offset ----------
__global__ void scan_final_kernel(int n) {
    __shared__ int wsum[32];
    int t = threadIdx.x;
    int i = blockIdx.x * 1024 + t;
    int v = (i < n) ? d_deg[i] : 0;
    int x = v;
    #pragma unroll
    for (int o = 1; o < 32; o <<= 1) {
        int y = __shfl_up_sync(0xffffffffu, x, o);
        if ((t & 31) >= o) x += y;
    }
    if ((t & 31) == 31) wsum[t >> 5] = x;
    __syncthreads();
    if (t < 32) {
        int s = wsum[t];
        #pragma unroll
        for (int o = 1; o < 32; o <<= 1) {
            int y = __shfl_up_sync(0xffffffffu, s, o);
            if (t >= o) s += y;
        }
        wsum[t] = s;
    }
    __syncthreads();
    int warpOff = (t >= 32) ? wsum[(t >> 5) - 1] : 0;
    int excl = x + warpOff - v + d_blockoff[blockIdx.x];
    if (i < n) { d_rowptr[i] = excl; d_cursor[i] = excl; }
}

__global__ void fill_kernel(const int* __restrict__ src, const int* __restrict__ dst, int e) {
    int i = blockIdx.x * blockDim.x + threadIdx.x;
    if (i < e) {
        int pos = atomicAdd(&d_cursor[dst[i]], 1);
        d_colidx[pos] = src[i];
    }
}

// ---------------- fp32 GEMM: out[r][c] = dinv[r] * sum_k A[r][k] * W[k][c] ----------------
// BM=128 rows/block, BN=128 (full width), 256 threads, 8x8 per-thread tile,
// full W resident in shared, A staged in 16-deep k-chunks (transposed, padded).
template <int K>
__global__ void __launch_bounds__(256) gemm_scaled_kernel(
    const float* __restrict__ A, const float* __restrict__ W,
    float* __restrict__ out, int nrows)
{
    constexpr int BM = 128;
    constexpr int KC = 16;
    constexpr int SAP = 132;   // padded sA row stride (132*4=528, 528%16==0)
    extern __shared__ float smem[];
    float* sW = smem;             // K*128
    float* sA = smem + K * 128;   // KC * SAP

    int tid = threadIdx.x;
    // stage full W into shared
    for (int i = tid * 4; i < K * 128; i += 256 * 4) {
        *(float4*)(sW + i) = *(const float4*)(W + i);
    }

    int blockRow = blockIdx.x * BM;
    int tx = tid & 15;    // col group: cols tx*8 .. tx*8+7
    int ty = tid >> 4;    // row group: rows ty*8 .. ty*8+7
    float acc[8][8];
    #pragma unroll
    for (int i = 0; i < 8; i++)
        #pragma unroll
        for (int j = 0; j < 8; j++) acc[i][j] = 0.0f;

    int lr = tid >> 2;          // 0..63
    int lk = (tid & 3) * 4;     // 0,4,8,12

    for (int k0 = 0; k0 < K; k0 += KC) {
        __syncthreads();   // protect sA reuse (also orders first-use of sW)
        #pragma unroll
        for (int rr = lr; rr < BM; rr += 64) {
            int grow = blockRow + rr;
            float4 v = make_float4(0.f, 0.f, 0.f, 0.f);
            if (grow < nrows) v = *(const float4*)(A + (size_t)grow * K + k0 + lk);
            sA[(lk + 0) * SAP + rr] = v.x;
            sA[(lk + 1) * SAP + rr] = v.y;
            sA[(lk + 2) * SAP + rr] = v.z;
            sA[(lk + 3) * SAP + rr] = v.w;
        }
        __syncthreads();

        #pragma unroll
        for (int k = 0; k < KC; k++) {
            const float* wr = sW + (k0 + k) * 128 + tx * 8;
            float4 w0 = *(const float4*)wr;
            float4 w1 = *(const float4*)(wr + 4);
            const float* ar = sA + k * SAP + ty * 8;
            float4 a0 = *(const float4*)ar;
            float4 a1 = *(const float4*)(ar + 4);
            float av[8] = {a0.x, a0.y, a0.z, a0.w, a1.x, a1.y, a1.z, a1.w};
            float wv[8] = {w0.x, w0.y, w0.z, w0.w, w1.x, w1.y, w1.z, w1.w};
            #pragma unroll
            for (int i = 0; i < 8; i++)
                #pragma unroll
                for (int j = 0; j < 8; j++)
                    acc[i][j] = fmaf(av[i], wv[j], acc[i][j]);
        }
    }

    #pragma unroll
    for (int i = 0; i < 8; i++) {
        int grow = blockRow + ty * 8 + i;
        if (grow < nrows) {
            float di = d_dinv[grow];
            float4 o0 = make_float4(acc[i][0] * di, acc[i][1] * di, acc[i][2] * di, acc[i][3] * di);
            float4 o1 = make_float4(acc[i][4] * di, acc[i][5] * di, acc[i][6] * di, acc[i][7] * di);
            float* op = out + (size_t)grow * 128 + tx * 8;
            *(float4*)op = o0;
            *(float4*)(op + 4) = o1;
        }
    }
}

// ---------------- aggregation: hout[i] = relu?( dinv[i]*(sum_{src} hin[src] + hin[i]) + b ) ----
// hin is already row-scaled by dinv (GEMM epilogue). One warp per node, float4 lanes.
__global__ void agg_kernel(const float* __restrict__ hin, float* __restrict__ hout,
                           const float* __restrict__ b, int n, int do_relu)
{
    int lane = threadIdx.x & 31;
    int node = blockIdx.x * (blockDim.x >> 5) + (threadIdx.x >> 5);
    if (node >= n) return;
    const float4* h4 = (const float4*)hin;
    float4 acc = h4[(size_t)node * 32 + lane];   // self term: hin[i] (= h[i]*dinv[i])
    int e   = d_rowptr[node];
    int end = d_rowptr[node + 1];
    for (; e + 3 < end; e += 4) {
        int s0 = d_colidx[e], s1 = d_colidx[e + 1], s2 = d_colidx[e + 2], s3 = d_colidx[e + 3];
        float4 v0 = h4[(size_t)s0 * 32 + lane];
        float4 v1 = h4[(size_t)s1 * 32 + lane];
        float4 v2 = h4[(size_t)s2 * 32 + lane];
        float4 v3 = h4[(size_t)s3 * 32 + lane];
        acc.x += v0.x + v1.x + v2.x + v3.x;
        acc.y += v0.y + v1.y + v2.y + v3.y;
        acc.z += v0.z + v1.z + v2.z + v3.z;
        acc.w += v0.w + v1.w + v2.w + v3.w;
    }
    for (; e < end; e++) {
        int s = d_colidx[e];
        float4 v = h4[(size_t)s * 32 + lane];
        acc.x += v.x; acc.y += v.y; acc.z += v.z; acc.w += v.w;
    }
    float di = d_dinv[node];
    float4 bb = ((const float4*)b)[lane];
    float4 r;
    r.x = fmaf(acc.x, di, bb.x);
    r.y = fmaf(acc.y, di, bb.y);
    r.z = fmaf(acc.z, di, bb.z);
    r.w = fmaf(acc.w, di, bb.w);
    if (do_relu) {
        r.x = fmaxf(r.x, 0.f); r.y = fmaxf(r.y, 0.f);
        r.z = fmaxf(r.z, 0.f); r.w = fmaxf(r.w, 0.f);
    }
    ((float4*)hout)[(size_t)node * 32 + lane] = r;
}

// ---------------- decode: out[e] = dot(z[a[e]], z[b[e]]) over 128 dims ----------------
__global__ void decode_kernel(const int* __restrict__ eli, float* __restrict__ out, int el)
{
    int gw = (blockIdx.x * blockDim.x + threadIdx.x) >> 5;
    int lane = threadIdx.x & 31;
    if (gw >= el) return;
    int a = eli[gw];
    int b = eli[el + gw];
    const float4* z4 = (const float4*)d_z;
    float4 va = z4[(size_t)a * 32 + lane];
    float4 vb = z4[(size_t)b * 32 + lane];
    float s = va.x * vb.x + va.y * vb.y + va.z * vb.z + va.w * vb.w;
    #pragma unroll
    for (int o = 16; o > 0; o >>= 1) s += __shfl_xor_sync(0xffffffffu, s, o);
    if (lane == 0) out[gw] = s;
}

// ---------------- launch ----------------
extern "C" void kernel_launch(void* const* d_in, const int* in_sizes, int n_in,
                              void* d_out, int out_size)
{
    const float* x   = (const float*)d_in[0];
    const int*   ei  = (const int*)d_in[1];   // [2, E]: src then dst
    const int*   eli = (const int*)d_in[2];   // [2, EL]
    const float* W1  = (const float*)d_in[3];
    const float* b1  = (const float*)d_in[4];
    const float* W2  = (const float*)d_in[5];
    const float* b2  = (const float*)d_in[6];
    float* out = (float*)d_out;

    int n  = in_sizes[0] / DINC;
    int e  = in_sizes[1] / 2;
    int el = in_sizes[2] / 2;

    const int* src = ei;
    const int* dst = ei + e;

    // opt-in to large dynamic shared (idempotent; not a stream op)
    static bool attr_set = false;
    if (!attr_set) {
        cudaFuncSetAttribute(gemm_scaled_kernel<DINC>,
                             cudaFuncAttributeMaxDynamicSharedMemorySize, 160 * 1024);
        cudaFuncSetAttribute(gemm_scaled_kernel<DHC>,
                             cudaFuncAttributeMaxDynamicSharedMemorySize, 96 * 1024);
        attr_set = true;
    }

    float* hbuf; cudaGetSymbolAddress((void**)&hbuf, d_h);
    float* h1;   cudaGetSymbolAddress((void**)&h1,   d_h1);
    float* z;    cudaGetSymbolAddress((void**)&z,    d_z);

    int nb = (n + 1023) / 1024;

    // 1) CSR build (hierarchical scan instead of single-block scan)
    zero_deg_kernel<<<(n + 255) / 256, 256>>>(n);
    count_deg_kernel<<<(e + 255) / 256, 256>>>(dst, e);
    dinv_kernel<<<(n + 255) / 256, 256>>>(n);
    scan_reduce_kernel<<<nb, 1024>>>(n);
    scan_spine_kernel<<<1, 1024>>>(nb, n);
    scan_final_kernel<<<nb, 1024>>>(n);
    fill_kernel<<<(e + 255) / 256, 256>>>(src, dst, e);

    // 2) layer 1: h = (x@W1)*dinv ; h1 = relu(dinv*(gather-sum + self) + b1)
    {
        size_t smem = (size_t)(DINC * 128 + 16 * 132) * sizeof(float);
        gemm_scaled_kernel<DINC><<<(n + 127) / 128, 256, smem>>>(x, W1, hbuf, n);
        agg_kernel<<<(n + 7) / 8, 256>>>(hbuf, h1, b1, n, 1);
    }

    // 3) layer 2
    {
        size_t smem = (size_t)(DHC * 128 + 16 * 132) * sizeof(float);
        gemm_scaled_kernel<DHC><<<(n + 127) / 128, 256, smem>>>(h1, W2, hbuf, n);
        agg_kernel<<<(n + 7) / 8, 256>>>(hbuf, z, b2, n, 0);
    }

    // 4) decode
    decode_kernel<<<(el * 32 + 255) / 256, 256>>>(eli, out, el);
}

// round 4
// speedup vs baseline: 1.7122x; 1.5293x over previous
#include <cuda_runtime.h>
#include <cuda_bf16.h>
#include <cstdint>

// Problem constants (fixed by the dataset)
#define NN   100000
#define EE   1600000
#define DINC 256
#define DHC  128
#define NBLK ((NN + 1023) / 1024)   // 98 scan blocks

// ================= warp-MMA helpers (portable PTX, sm_80+) =================
__device__ __forceinline__ uint32_t smem_to_u32(const void* p) {
    uint32_t a;
    asm("{ .reg .u64 t; cvta.to.shared.u64 t, %1; cvt.u32.u64 %0, t; }" : "=r"(a) : "l"(p));
    return a;
}
__device__ __forceinline__ void ldsm_x4(uint32_t* r, uint32_t addr) {
    asm volatile("ldmatrix.sync.aligned.m8n8.x4.shared.b16 {%0,%1,%2,%3}, [%4];"
        : "=r"(r[0]), "=r"(r[1]), "=r"(r[2]), "=r"(r[3]) : "r"(addr));
}
__device__ __forceinline__ void mma16816(float* c, const uint32_t* a, const uint32_t* b) {
    asm volatile("mma.sync.aligned.m16n8k16.row.col.f32.bf16.bf16.f32 "
        "{%0,%1,%2,%3}, {%4,%5,%6,%7}, {%8,%9}, {%0,%1,%2,%3};"
        : "+f"(c[0]), "+f"(c[1]), "+f"(c[2]), "+f"(c[3])
        : "r"(a[0]), "r"(a[1]), "r"(a[2]), "r"(a[3]), "r"(b[0]), "r"(b[1]));
}

// ---------------- static device scratch (no allocations allowed) ----------------
__device__ int   d_deg[NN];
__device__ int   d_cursor[NN];
__device__ int   d_rowptr[NN + 1];
__device__ int   d_colidx[EE];
__device__ int   d_blocksum[NBLK];
__device__ int   d_blockoff[NBLK];
__device__ float d_dinv[NN];
__device__ float d_h  [(size_t)NN * DHC];  // GEMM output (dinv-scaled)
__device__ float d_h1 [(size_t)NN * DHC];  // layer-1 output (post agg+relu)
__device__ float d_z  [(size_t)NN * DHC];  // layer-2 output
// Pre-swizzled bf16 hi/lo images of W^T, chunked [128 n][64 k] per chunk (16KB = 1024 uint4)
__device__ uint4 d_B1hi[4096];  // 4 chunks (K=256)
__device__ uint4 d_B1lo[4096];
__device__ uint4 d_B2hi[2048];  // 2 chunks (K=128)
__device__ uint4 d_B2lo[2048];

// ---------------- degree count ----------------
__global__ void zero_deg_kernel(int n) {
    int i = blockIdx.x * blockDim.x + threadIdx.x;
    if (i < n) d_deg[i] = 0;
}
__global__ void count_deg_kernel(const int* __restrict__ dst, int e) {
    int i = blockIdx.x * blockDim.x + threadIdx.x;
    if (i < e) atomicAdd(&d_deg[dst[i]], 1);
}
__global__ void dinv_kernel(int n) {
    int i = blockIdx.x * blockDim.x + threadIdx.x;
    if (i < n) d_dinv[i] = rsqrtf((float)d_deg[i] + 1.0f);
}

// ---------------- hierarchical scan ----------------
__global__ void scan_reduce_kernel(int n) {
    __shared__ int wsum[32];
    int t = threadIdx.x;
    int i = blockIdx.x * 1024 + t;
    int v = (i < n) ? d_deg[i] : 0;
    #pragma unroll
    for (int o = 16; o > 0; o >>= 1) v += __shfl_xor_sync(0xffffffffu, v, o);
    if ((t & 31) == 0) wsum[t >> 5] = v;
    __syncthreads();
    if (t < 32) {
        int s = wsum[t];
        #pragma unroll
        for (int o = 16; o > 0; o >>= 1) s += __shfl_xor_sync(0xffffffffu, s, o);
        if (t == 0) d_blocksum[blockIdx.x] = s;
    }
}
__global__ void scan_spine_kernel(int nb, int n) {
    __shared__ int wsum[32];
    int t = threadIdx.x;
    int v = (t < nb) ? d_blocksum[t] : 0;
    int x = v;
    #pragma unroll
    for (int o = 1; o < 32; o <<= 1) {
        int y = __shfl_up_sync(0xffffffffu, x, o);
        if ((t & 31) >= o) x += y;
    }
    if ((t & 31) == 31) wsum[t >> 5] = x;
    __syncthreads();
    if (t < 32) {
        int s = wsum[t];
        #pragma unroll
        for (int o = 1; o < 32; o <<= 1) {
            int y = __shfl_up_sync(0xffffffffu, s, o);
            if (t >= o) s += y;
        }
        wsum[t] = s;
    }
    __syncthreads();
    int warpOff = (t >= 32) ? wsum[(t >> 5) - 1] : 0;
    int excl = x + warpOff - v;
    if (t < nb) d_blockoff[t] = excl;
    if (t == 1023) d_rowptr[n] = x + warpOff;
}
__global__ void scan_final_kernel(int n) {
    __shared__ int wsum[32];
    int t = threadIdx.x;
    int i = blockIdx.x * 1024 + t;
    int v = (i < n) ? d_deg[i] : 0;
    int x = v;
    #pragma unroll
    for (int o = 1; o < 32; o <<= 1) {
        int y = __shfl_up_sync(0xffffffffu, x, o);
        if ((t & 31) >= o) x += y;
    }
    if ((t & 31) == 31) wsum[t >> 5] = x;
    __syncthreads();
    if (t < 32) {
        int s = wsum[t];
        #pragma unroll
        for (int o = 1; o < 32; o <<= 1) {
            int y = __shfl_up_sync(0xffffffffu, s, o);
            if (t >= o) s += y;
        }
        wsum[t] = s;
    }
    __syncthreads();
    int warpOff = (t >= 32) ? wsum[(t >> 5) - 1] : 0;
    int excl = x + warpOff - v + d_blockoff[blockIdx.x];
    if (i < n) { d_rowptr[i] = excl; d_cursor[i] = excl; }
}
__global__ void fill_kernel(const int* __restrict__ src, const int* __restrict__ dst, int e) {
    int i = blockIdx.x * blockDim.x + threadIdx.x;
    if (i < e) {
        int pos = atomicAdd(&d_cursor[dst[i]], 1);
        d_colidx[pos] = src[i];
    }
}

// ---------------- prep: W[k][c] -> W^T bf16 hi/lo, chunked [128 c][64 k], XOR-swizzled ----
__global__ void prep_w_kernel(const float* __restrict__ W, uint4* __restrict__ hi_img,
                              uint4* __restrict__ lo_img, int K) {
    int idx = blockIdx.x * blockDim.x + threadIdx.x;
    if (idx >= K * 128) return;
    int k = idx >> 7;          // 0..K-1
    int c = idx & 127;         // output col = MMA n index
    int chunk = k >> 6;
    int kl = k & 63;
    float v = W[k * 128 + c];
    __nv_bfloat16 hv = __float2bfloat16(v);
    __nv_bfloat16 lv = __float2bfloat16(v - __bfloat162float(hv));
    uint32_t off = (uint32_t)c * 128 + (((uint32_t)kl * 2) ^ (((uint32_t)c & 7) << 4));
    size_t e = (size_t)chunk * 8192 + (off >> 1);
    ((__nv_bfloat16*)hi_img)[e] = hv;
    ((__nv_bfloat16*)lo_img)[e] = lv;
}

// ---------------- warp-MMA GEMM: out[r][c] = dinv[r] * sum_k A[r][k] * W[k][c] ----------------
// bf16 3-pass split (AhBh + AlBh + AhBl), fp32 accumulate.
// 256 threads = 8 warps; block tile 128x128; warp tile 64x32; K chunks of 64.
#define GM_SA_HI 0
#define GM_SA_LO 16384
#define GM_SB_HI 32768
#define GM_SB_LO 49152
#define GM_SMEM  65536

template <int K>
__global__ void __launch_bounds__(256) gemm_mma_kernel(
    const float* __restrict__ A, const uint4* __restrict__ Bhi, const uint4* __restrict__ Blo,
    float* __restrict__ out, int nrows)
{
    constexpr int NCH = K / 64;
    extern __shared__ char smem[];
    uint32_t sb = smem_to_u32(smem);
    int tid = threadIdx.x;
    int wid = tid >> 5;
    int lane = tid & 31;
    int blockRow = blockIdx.x * 128;
    int wm = wid & 1;          // 2 m-halves of 64
    int wn = wid >> 1;         // 4 n-quarters of 32

    float C[4][4][4];
    #pragma unroll
    for (int a = 0; a < 4; a++)
        #pragma unroll
        for (int b = 0; b < 4; b++)
            #pragma unroll
            for (int c = 0; c < 4; c++) C[a][b][c] = 0.0f;

    // precompute ldmatrix lane roles
    int li = lane >> 3;   // matrix index 0..3
    int lj = lane & 7;    // row-within-matrix

    for (int ch = 0; ch < NCH; ch++) {
        __syncthreads();   // previous chunk's reads done before overwrite

        // B chunk copy (pre-swizzled, 1024 uint4 per buffer)
        {
            const uint4* bh = Bhi + (size_t)ch * 1024;
            const uint4* bl = Blo + (size_t)ch * 1024;
            #pragma unroll
            for (int j = 0; j < 4; j++) {
                int i = tid + j * 256;
                *(uint4*)(smem + GM_SB_HI + i * 16) = bh[i];
                *(uint4*)(smem + GM_SB_LO + i * 16) = bl[i];
            }
        }
        // A chunk: load fp32, split to bf16 hi/lo, swizzled store (128 rows x 64 k)
        {
            #pragma unroll
            for (int j = 0; j < 8; j++) {
                int idx4 = tid + j * 256;
                int r = idx4 >> 4;             // 0..127
                int kq = (idx4 & 15) << 2;     // 0,4,...,60
                int grow = blockRow + r;
                float4 v = make_float4(0.f, 0.f, 0.f, 0.f);
                if (grow < nrows)
                    v = *(const float4*)(A + (size_t)grow * K + ch * 64 + kq);
                __nv_bfloat16 h0 = __float2bfloat16(v.x), h1 = __float2bfloat16(v.y);
                __nv_bfloat16 h2 = __float2bfloat16(v.z), h3 = __float2bfloat16(v.w);
                __nv_bfloat16 l0 = __float2bfloat16(v.x - __bfloat162float(h0));
                __nv_bfloat16 l1 = __float2bfloat16(v.y - __bfloat162float(h1));
                __nv_bfloat16 l2 = __float2bfloat16(v.z - __bfloat162float(h2));
                __nv_bfloat16 l3 = __float2bfloat16(v.w - __bfloat162float(h3));
                uint32_t off = (uint32_t)r * 128 + (((uint32_t)kq * 2) ^ (((uint32_t)r & 7) << 4));
                uint2 hp, lp;
                hp.x = ((uint32_t)__bfloat16_as_ushort(h1) << 16) | __bfloat16_as_ushort(h0);
                hp.y = ((uint32_t)__bfloat16_as_ushort(h3) << 16) | __bfloat16_as_ushort(h2);
                lp.x = ((uint32_t)__bfloat16_as_ushort(l1) << 16) | __bfloat16_as_ushort(l0);
                lp.y = ((uint32_t)__bfloat16_as_ushort(l3) << 16) | __bfloat16_as_ushort(l2);
                *(uint2*)(smem + GM_SA_HI + off) = hp;
                *(uint2*)(smem + GM_SA_LO + off) = lp;
            }
        }
        __syncthreads();

        #pragma unroll
        for (int ks = 0; ks < 4; ks++) {
            // A fragments: 4 m-tiles (16 rows each), ldmatrix x4 -> regs a0..a3
            uint32_t ahi[4][4], alo[4][4];
            #pragma unroll
            for (int mt = 0; mt < 4; mt++) {
                int row = wm * 64 + mt * 16 + lj + (li & 1) * 8;
                int kb  = ks * 32 + (li >> 1) * 16;
                uint32_t addr = sb + GM_SA_HI + (uint32_t)row * 128
                              + ((uint32_t)kb ^ (((uint32_t)row & 7) << 4));
                ldsm_x4(ahi[mt], addr);
                ldsm_x4(alo[mt], addr + 16384);
            }
            // B fragments: 2 n-tile-pairs; x4 covers two 16x8 n-tiles
            uint32_t bhi[2][4], blo[2][4];
            #pragma unroll
            for (int np = 0; np < 2; np++) {
                int row = wn * 32 + np * 16 + lj + (li >> 1) * 8;
                int kb  = ks * 32 + (li & 1) * 16;
                uint32_t addr = sb + GM_SB_HI + (uint32_t)row * 128
                              + ((uint32_t)kb ^ (((uint32_t)row & 7) << 4));
                ldsm_x4(bhi[np], addr);
                ldsm_x4(blo[np], addr + 16384);
            }
            #pragma unroll
            for (int mt = 0; mt < 4; mt++) {
                #pragma unroll
                for (int np = 0; np < 2; np++) {
                    #pragma unroll
                    for (int h = 0; h < 2; h++) {
                        float* cc = C[mt][np * 2 + h];
                        mma16816(cc, ahi[mt], &bhi[np][h * 2]);
                        mma16816(cc, alo[mt], &bhi[np][h * 2]);
                        mma16816(cc, ahi[mt], &blo[np][h * 2]);
                    }
                }
            }
        }
    }

    // epilogue: scale by dinv, float2 stores
    int g = lane >> 2, tig = lane & 3;
    #pragma unroll
    for (int mt = 0; mt < 4; mt++) {
        int r0 = blockRow + wm * 64 + mt * 16 + g;
        int r1 = r0 + 8;
        float di0 = (r0 < nrows) ? d_dinv[r0] : 0.f;
        float di1 = (r1 < nrows) ? d_dinv[r1] : 0.f;
        #pragma unroll
        for (int nt = 0; nt < 4; nt++) {
            int col = wn * 32 + nt * 8 + tig * 2;
            if (r0 < nrows) {
                float2 o = make_float2(C[mt][nt][0] * di0, C[mt][nt][1] * di0);
                *(float2*)(out + (size_t)r0 * 128 + col) = o;
            }
            if (r1 < nrows) {
                float2 o = make_float2(C[mt][nt][2] * di1, C[mt][nt][3] * di1);
                *(float2*)(out + (size_t)r1 * 128 + col) = o;
            }
        }
    }
}

// ---------------- aggregation: hout[i] = relu?( dinv[i]*(sum_{src} hin[src] + hin[i]) + b ) ----
__global__ void agg_kernel(const float* __restrict__ hin, float* __restrict__ hout,
                           const float* __restrict__ b, int n, int do_relu)
{
    int lane = threadIdx.x & 31;
    int node = blockIdx.x * (blockDim.x >> 5) + (threadIdx.x >> 5);
    if (node >= n) return;
    const float4* h4 = (const float4*)hin;
    float4 acc = h4[(size_t)node * 32 + lane];   // self term (already dinv-scaled)
    int e   = d_rowptr[node];
    int end = d_rowptr[node + 1];
    for (; e + 3 < end; e += 4) {
        int s0 = d_colidx[e], s1 = d_colidx[e + 1], s2 = d_colidx[e + 2], s3 = d_colidx[e + 3];
        float4 v0 = h4[(size_t)s0 * 32 + lane];
        float4 v1 = h4[(size_t)s1 * 32 + lane];
        float4 v2 = h4[(size_t)s2 * 32 + lane];
        float4 v3 = h4[(size_t)s3 * 32 + lane];
        acc.x += v0.x + v1.x + v2.x + v3.x;
        acc.y += v0.y + v1.y + v2.y + v3.y;
        acc.z += v0.z + v1.z + v2.z + v3.z;
        acc.w += v0.w + v1.w + v2.w + v3.w;
    }
    for (; e < end; e++) {
        int s = d_colidx[e];
        float4 v = h4[(size_t)s * 32 + lane];
        acc.x += v.x; acc.y += v.y; acc.z += v.z; acc.w += v.w;
    }
    float di = d_dinv[node];
    float4 bb = ((const float4*)b)[lane];
    float4 r;
    r.x = fmaf(acc.x, di, bb.x);
    r.y = fmaf(acc.y, di, bb.y);
    r.z = fmaf(acc.z, di, bb.z);
    r.w = fmaf(acc.w, di, bb.w);
    if (do_relu) {
        r.x = fmaxf(r.x, 0.f); r.y = fmaxf(r.y, 0.f);
        r.z = fmaxf(r.z, 0.f); r.w = fmaxf(r.w, 0.f);
    }
    ((float4*)hout)[(size_t)node * 32 + lane] = r;
}

// ---------------- decode: out[e] = dot(z[a[e]], z[b[e]]) over 128 dims ----------------
__global__ void decode_kernel(const int* __restrict__ eli, float* __restrict__ out, int el)
{
    int gw = (blockIdx.x * blockDim.x + threadIdx.x) >> 5;
    int lane = threadIdx.x & 31;
    if (gw >= el) return;
    int a = eli[gw];
    int b = eli[el + gw];
    const float4* z4 = (const float4*)d_z;
    float4 va = z4[(size_t)a * 32 + lane];
    float4 vb = z4[(size_t)b * 32 + lane];
    float s = va.x * vb.x + va.y * vb.y + va.z * vb.z + va.w * vb.w;
    #pragma unroll
    for (int o = 16; o > 0; o >>= 1) s += __shfl_xor_sync(0xffffffffu, s, o);
    if (lane == 0) out[gw] = s;
}

// ---------------- launch ----------------
extern "C" void kernel_launch(void* const* d_in, const int* in_sizes, int n_in,
                              void* d_out, int out_size)
{
    const float* x   = (const float*)d_in[0];
    const int*   ei  = (const int*)d_in[1];   // [2, E]: src then dst
    const int*   eli = (const int*)d_in[2];   // [2, EL]
    const float* W1  = (const float*)d_in[3];
    const float* b1  = (const float*)d_in[4];
    const float* W2  = (const float*)d_in[5];
    const float* b2  = (const float*)d_in[6];
    float* out = (float*)d_out;

    int n  = in_sizes[0] / DINC;
    int e  = in_sizes[1] / 2;
    int el = in_sizes[2] / 2;

    const int* src = ei;
    const int* dst = ei + e;

    static bool attr_set = false;
    if (!attr_set) {
        cudaFuncSetAttribute(gemm_mma_kernel<DINC>, cudaFuncAttributeMaxDynamicSharedMemorySize, GM_SMEM);
        cudaFuncSetAttribute(gemm_mma_kernel<DHC>,  cudaFuncAttributeMaxDynamicSharedMemorySize, GM_SMEM);
        attr_set = true;
    }

    float* hbuf; cudaGetSymbolAddress((void**)&hbuf, d_h);
    float* h1;   cudaGetSymbolAddress((void**)&h1,   d_h1);
    float* z;    cudaGetSymbolAddress((void**)&z,    d_z);
    uint4* B1h;  cudaGetSymbolAddress((void**)&B1h,  d_B1hi);
    uint4* B1l;  cudaGetSymbolAddress((void**)&B1l,  d_B1lo);
    uint4* B2h;  cudaGetSymbolAddress((void**)&B2h,  d_B2hi);
    uint4* B2l;  cudaGetSymbolAddress((void**)&B2l,  d_B2lo);

    int nb = (n + 1023) / 1024;
    int gGemm = (n + 127) / 128;

    // 1) CSR build + weight prep
    zero_deg_kernel<<<(n + 255) / 256, 256>>>(n);
    count_deg_kernel<<<(e + 255) / 256, 256>>>(dst, e);
    dinv_kernel<<<(n + 255) / 256, 256>>>(n);
    scan_reduce_kernel<<<nb, 1024>>>(n);
    scan_spine_kernel<<<1, 1024>>>(nb, n);
    scan_final_kernel<<<nb, 1024>>>(n);
    fill_kernel<<<(e + 255) / 256, 256>>>(src, dst, e);
    prep_w_kernel<<<(DINC * 128 + 255) / 256, 256>>>(W1, B1h, B1l, DINC);
    prep_w_kernel<<<(DHC * 128 + 255) / 256, 256>>>(W2, B2h, B2l, DHC);

    // 2) layer 1
    gemm_mma_kernel<DINC><<<gGemm, 256, GM_SMEM>>>(x, B1h, B1l, hbuf, n);
    agg_kernel<<<(n + 7) / 8, 256>>>(hbuf, h1, b1, n, 1);

    // 3) layer 2
    gemm_mma_kernel<DHC><<<gGemm, 256, GM_SMEM>>>(h1, B2h, B2l, hbuf, n);
    agg_kernel<<<(n + 7) / 8, 256>>>(hbuf, z, b2, n, 0);

    // 4) decode
    decode_kernel<<<(el * 32 + 255) / 256, 256>>>(eli, out, el);
}